// round 8
// baseline (speedup 1.0000x reference)
#include <cuda_runtime.h>
#include <cstdint>
#include <cstddef>

// Problem constants
namespace {
constexpr int Bn = 64;      // batch
constexpr int Gd = 307;     // graph dim (M)
constexpr int Ed = 64;
constexpr int Td = 12;
constexpr int Kd = Ed * Td; // 768 contraction
constexpr int Nd = Ed * Td; // 768 output feature
constexpr int BM = 128, BN = 128, BK = 16;
constexpr int SST = 136;    // padded smem row stride (floats): +8 kills frag-LDS bank conflicts
constexpr int NTHREADS = 256;
}

__device__ __forceinline__ uint32_t f2tf(float f) {
    uint32_t u;
    asm("cvt.rna.tf32.f32 %0, %1;" : "=r"(u) : "f"(f));
    return u;
}

__device__ __forceinline__ void mma_tf32(float c[4], const uint32_t a[4], const uint32_t b[2]) {
    asm volatile(
        "mma.sync.aligned.m16n8k8.row.col.f32.tf32.tf32.f32 "
        "{%0,%1,%2,%3}, {%4,%5,%6,%7}, {%8,%9}, {%0,%1,%2,%3};\n"
        : "+f"(c[0]), "+f"(c[1]), "+f"(c[2]), "+f"(c[3])
        : "r"(a[0]), "r"(a[1]), "r"(a[2]), "r"(a[3]), "r"(b[0]), "r"(b[1]));
}

__global__ __launch_bounds__(NTHREADS, 2)
void talinear_kernel(const float* __restrict__ inp,    // [B, G, E, T]
                     const int*   __restrict__ week,   // [B]
                     const int*   __restrict__ date,   // [B]
                     const float* __restrict__ wwsp,   // [7,  T, E, E, T]
                     const float* __restrict__ wbsp,   // [7,  G, E, T]
                     const float* __restrict__ dwsp,   // [288,T, E, E, T]
                     const float* __restrict__ dbsp,   // [288,G, E, T]
                     float*       __restrict__ out)    // [B, G, E, T]
{
    __shared__ __align__(16) uint32_t As[2][BK * SST];  // k-major: [k][m]
    __shared__ __align__(16) uint32_t Bs[2][BK * SST];  // [k][n]

    const int b   = blockIdx.z;
    const int m0  = blockIdx.y * BM;
    const int n0  = blockIdx.x * BN;
    const int tid = threadIdx.x;
    const int ws  = week[b];
    const int ds  = date[b];

    // ---------- global->reg staging mapping ----------
    // A tile: 128 rows x 16 floats = 512 float4, 2 per thread
    const int arow0 = tid >> 2;        // 0..63
    const int arow1 = arow0 + 64;      // 64..127
    const int af4   = tid & 3;         // which float4 within row chunk
    const bool av0  = (m0 + arow0) < Gd;
    const bool av1  = (m0 + arow1) < Gd;
    const float* pa0 = inp + ((size_t)b * Gd + (av0 ? (m0 + arow0) : 0)) * Kd + af4 * 4;
    const float* pa1 = inp + ((size_t)b * Gd + (av1 ? (m0 + arow1) : 0)) * Kd + af4 * 4;

    // B tile: 16 rows x 32 float4 = 512 float4, 2 per thread (rows brow0, brow0+8)
    const int brow0 = tid >> 5;        // 0..7
    const int bf4   = tid & 31;        // 0..31

    float4 ar0, ar1, br0, br1;

    auto ldg = [&](int k0) {
        ar0 = make_float4(0.f, 0.f, 0.f, 0.f);
        ar1 = ar0;
        if (av0) ar0 = *reinterpret_cast<const float4*>(pa0 + k0);
        if (av1) ar1 = *reinterpret_cast<const float4*>(pa1 + k0);
        {
            int k = k0 + brow0;
            int t = k % Td, e = k / Td;
            size_t wo = ((size_t)(ws * Td + t) * Ed + e) * (size_t)Nd + n0 + bf4 * 4;
            size_t dofs = ((size_t)(ds * Td + t) * Ed + e) * (size_t)Nd + n0 + bf4 * 4;
            float4 w = *reinterpret_cast<const float4*>(wwsp + wo);
            float4 d = *reinterpret_cast<const float4*>(dwsp + dofs);
            br0 = make_float4(0.5f * (w.x + d.x), 0.5f * (w.y + d.y),
                              0.5f * (w.z + d.z), 0.5f * (w.w + d.w));
        }
        {
            int k = k0 + brow0 + 8;
            int t = k % Td, e = k / Td;
            size_t wo = ((size_t)(ws * Td + t) * Ed + e) * (size_t)Nd + n0 + bf4 * 4;
            size_t dofs = ((size_t)(ds * Td + t) * Ed + e) * (size_t)Nd + n0 + bf4 * 4;
            float4 w = *reinterpret_cast<const float4*>(wwsp + wo);
            float4 d = *reinterpret_cast<const float4*>(dwsp + dofs);
            br1 = make_float4(0.5f * (w.x + d.x), 0.5f * (w.y + d.y),
                              0.5f * (w.z + d.z), 0.5f * (w.w + d.w));
        }
    };

    auto sts = [&](int buf) {
        uint32_t* A = As[buf];
        // transposed scatter: As[k][m], convert to tf32 once per element
        A[(af4 * 4 + 0) * SST + arow0] = f2tf(ar0.x);
        A[(af4 * 4 + 1) * SST + arow0] = f2tf(ar0.y);
        A[(af4 * 4 + 2) * SST + arow0] = f2tf(ar0.z);
        A[(af4 * 4 + 3) * SST + arow0] = f2tf(ar0.w);
        A[(af4 * 4 + 0) * SST + arow1] = f2tf(ar1.x);
        A[(af4 * 4 + 1) * SST + arow1] = f2tf(ar1.y);
        A[(af4 * 4 + 2) * SST + arow1] = f2tf(ar1.z);
        A[(af4 * 4 + 3) * SST + arow1] = f2tf(ar1.w);
        uint4 p0 = make_uint4(f2tf(br0.x), f2tf(br0.y), f2tf(br0.z), f2tf(br0.w));
        uint4 p1 = make_uint4(f2tf(br1.x), f2tf(br1.y), f2tf(br1.z), f2tf(br1.w));
        *reinterpret_cast<uint4*>(&Bs[buf][(size_t)brow0 * SST + bf4 * 4]) = p0;
        *reinterpret_cast<uint4*>(&Bs[buf][(size_t)(brow0 + 8) * SST + bf4 * 4]) = p1;
    };

    // ---------- warp/fragment mapping ----------
    const int warp = tid >> 5;
    const int lane = tid & 31;
    const int lg = lane >> 2;          // groupID
    const int lt = lane & 3;           // thread in group
    const int mW = (warp & 1) * 64;    // 2 warps along M
    const int nW = (warp >> 1) * 32;   // 4 warps along N

    float acc[4][4][4];
#pragma unroll
    for (int i = 0; i < 4; ++i)
#pragma unroll
        for (int j = 0; j < 4; ++j)
#pragma unroll
            for (int r = 0; r < 4; ++r) acc[i][j][r] = 0.f;

    auto compute = [&](int buf) {
        const uint32_t* A  = As[buf];
        const uint32_t* Bt = Bs[buf];
#pragma unroll
        for (int ks = 0; ks < 2; ++ks) {
            const int kb = ks * 8;
            uint32_t af[4][4];
#pragma unroll
            for (int i = 0; i < 4; ++i) {
                int col = mW + 16 * i + lg;
                af[i][0] = A[(kb + lt) * SST + col];
                af[i][1] = A[(kb + lt) * SST + col + 8];
                af[i][2] = A[(kb + lt + 4) * SST + col];
                af[i][3] = A[(kb + lt + 4) * SST + col + 8];
            }
            uint32_t bf[4][2];
#pragma unroll
            for (int j = 0; j < 4; ++j) {
                int col = nW + 8 * j + lg;
                bf[j][0] = Bt[(kb + lt) * SST + col];
                bf[j][1] = Bt[(kb + lt + 4) * SST + col];
            }
#pragma unroll
            for (int i = 0; i < 4; ++i)
#pragma unroll
                for (int j = 0; j < 4; ++j)
                    mma_tf32(acc[i][j], af[i], bf[j]);
        }
    };

    // ---------- pipelined mainloop: K = 48 tiles of 16 ----------
    ldg(0);
    sts(0);
    __syncthreads();
    ldg(BK);

#pragma unroll 2
    for (int kt = 0; kt < 46; ++kt) {
        compute(kt & 1);
        sts((kt + 1) & 1);
        __syncthreads();
        ldg((kt + 2) * BK);
    }
    compute(0);   // kt = 46
    sts(1);
    __syncthreads();
    compute(1);   // kt = 47

    // ---------- epilogue: bias gather + average + LeakyReLU ----------
#pragma unroll
    for (int i = 0; i < 4; ++i) {
        const int rbase = m0 + mW + 16 * i + lg;
#pragma unroll
        for (int j = 0; j < 4; ++j) {
            const int c = n0 + nW + 8 * j + lt * 2;
#pragma unroll
            for (int h = 0; h < 2; ++h) {
                const int r = rbase + h * 8;
                if (r < Gd) {
                    size_t biw = ((size_t)ws * Gd + r) * Nd + c;
                    size_t bid = ((size_t)ds * Gd + r) * Nd + c;
                    float2 w2 = *reinterpret_cast<const float2*>(wbsp + biw);
                    float2 d2 = *reinterpret_cast<const float2*>(dbsp + bid);
                    float x0 = acc[i][j][2 * h + 0] + 0.5f * (w2.x + d2.x);
                    float x1 = acc[i][j][2 * h + 1] + 0.5f * (w2.y + d2.y);
                    x0 = x0 > 0.f ? x0 : 0.3f * x0;
                    x1 = x1 > 0.f ? x1 : 0.3f * x1;
                    *reinterpret_cast<float2*>(out + ((size_t)b * Gd + r) * Nd + c) =
                        make_float2(x0, x1);
                }
            }
        }
    }
}

extern "C" void kernel_launch(void* const* d_in, const int* in_sizes, int n_in,
                              void* d_out, int out_size) {
    (void)in_sizes; (void)n_in; (void)out_size;
    const float* inp  = (const float*)d_in[0];
    const int*   week = (const int*)d_in[1];
    const int*   date = (const int*)d_in[2];
    const float* wwsp = (const float*)d_in[3];
    const float* wbsp = (const float*)d_in[4];
    const float* dwsp = (const float*)d_in[5];
    const float* dbsp = (const float*)d_in[6];
    float* out = (float*)d_out;

    dim3 grid(Nd / BN, (Gd + BM - 1) / BM, Bn);  // (6, 3, 64)
    talinear_kernel<<<grid, NTHREADS>>>(inp, week, date, wwsp, wbsp, dwsp, dbsp, out);
}

// round 9
// speedup vs baseline: 1.0021x; 1.0021x over previous
#include <cuda_runtime.h>
#include <cstdint>
#include <cstddef>

// Problem constants
namespace {
constexpr int Bn = 64;      // batch
constexpr int Gd = 307;     // graph dim (M)
constexpr int Ed = 64;
constexpr int Td = 12;
constexpr int Kd = Ed * Td; // 768 contraction
constexpr int Nd = Ed * Td; // 768 output feature
constexpr int BM = 128, BN = 128, BK = 16;
constexpr int SST = 136;    // padded smem row stride (floats): +8 kills frag-LDS bank conflicts
constexpr int NTHREADS = 256;
}

__device__ __forceinline__ uint32_t f2tf(float f) {
    uint32_t u;
    asm("cvt.rna.tf32.f32 %0, %1;" : "=r"(u) : "f"(f));
    return u;
}

__device__ __forceinline__ void mma_tf32(float c[4], const uint32_t a[4], const uint32_t b[2]) {
    asm volatile(
        "mma.sync.aligned.m16n8k8.row.col.f32.tf32.tf32.f32 "
        "{%0,%1,%2,%3}, {%4,%5,%6,%7}, {%8,%9}, {%0,%1,%2,%3};\n"
        : "+f"(c[0]), "+f"(c[1]), "+f"(c[2]), "+f"(c[3])
        : "r"(a[0]), "r"(a[1]), "r"(a[2]), "r"(a[3]), "r"(b[0]), "r"(b[1]));
}

__global__ __launch_bounds__(NTHREADS, 2)
void talinear_kernel(const float* __restrict__ inp,    // [B, G, E, T]
                     const int*   __restrict__ week,   // [B]
                     const int*   __restrict__ date,   // [B]
                     const float* __restrict__ wwsp,   // [7,  T, E, E, T]
                     const float* __restrict__ wbsp,   // [7,  G, E, T]
                     const float* __restrict__ dwsp,   // [288,T, E, E, T]
                     const float* __restrict__ dbsp,   // [288,G, E, T]
                     float*       __restrict__ out)    // [B, G, E, T]
{
    __shared__ __align__(16) uint32_t As[2][BK * SST];  // k-major: [k][m]
    __shared__ __align__(16) uint32_t Bs[2][BK * SST];  // [k][n]

    const int b   = blockIdx.z;
    const int m0  = blockIdx.y * BM;
    const int n0  = blockIdx.x * BN;
    const int tid = threadIdx.x;
    const int ws  = week[b];
    const int ds  = date[b];

    // ---------- global->reg staging mapping ----------
    // A tile: 128 rows x 16 floats = 512 float4, 2 per thread
    const int arow0 = tid >> 2;        // 0..63
    const int arow1 = arow0 + 64;      // 64..127
    const int af4   = tid & 3;         // which float4 within row chunk
    const bool av0  = (m0 + arow0) < Gd;
    const bool av1  = (m0 + arow1) < Gd;
    const float* pa0 = inp + ((size_t)b * Gd + (av0 ? (m0 + arow0) : 0)) * Kd + af4 * 4;
    const float* pa1 = inp + ((size_t)b * Gd + (av1 ? (m0 + arow1) : 0)) * Kd + af4 * 4;

    // B tile: 16 rows x 32 float4 = 512 float4, 2 per thread (rows brow0, brow0+8)
    const int brow0 = tid >> 5;        // 0..7
    const int bf4   = tid & 31;        // 0..31

    float4 ar0, ar1, br0, br1;

    auto ldg = [&](int k0) {
        ar0 = make_float4(0.f, 0.f, 0.f, 0.f);
        ar1 = ar0;
        if (av0) ar0 = *reinterpret_cast<const float4*>(pa0 + k0);
        if (av1) ar1 = *reinterpret_cast<const float4*>(pa1 + k0);
        {
            int k = k0 + brow0;
            int t = k % Td, e = k / Td;
            size_t wo = ((size_t)(ws * Td + t) * Ed + e) * (size_t)Nd + n0 + bf4 * 4;
            size_t dofs = ((size_t)(ds * Td + t) * Ed + e) * (size_t)Nd + n0 + bf4 * 4;
            float4 w = *reinterpret_cast<const float4*>(wwsp + wo);
            float4 d = *reinterpret_cast<const float4*>(dwsp + dofs);
            br0 = make_float4(0.5f * (w.x + d.x), 0.5f * (w.y + d.y),
                              0.5f * (w.z + d.z), 0.5f * (w.w + d.w));
        }
        {
            int k = k0 + brow0 + 8;
            int t = k % Td, e = k / Td;
            size_t wo = ((size_t)(ws * Td + t) * Ed + e) * (size_t)Nd + n0 + bf4 * 4;
            size_t dofs = ((size_t)(ds * Td + t) * Ed + e) * (size_t)Nd + n0 + bf4 * 4;
            float4 w = *reinterpret_cast<const float4*>(wwsp + wo);
            float4 d = *reinterpret_cast<const float4*>(dwsp + dofs);
            br1 = make_float4(0.5f * (w.x + d.x), 0.5f * (w.y + d.y),
                              0.5f * (w.z + d.z), 0.5f * (w.w + d.w));
        }
    };

    auto sts = [&](int buf) {
        uint32_t* A = As[buf];
        // transposed scatter: As[k][m], convert to tf32 once per element
        A[(af4 * 4 + 0) * SST + arow0] = f2tf(ar0.x);
        A[(af4 * 4 + 1) * SST + arow0] = f2tf(ar0.y);
        A[(af4 * 4 + 2) * SST + arow0] = f2tf(ar0.z);
        A[(af4 * 4 + 3) * SST + arow0] = f2tf(ar0.w);
        A[(af4 * 4 + 0) * SST + arow1] = f2tf(ar1.x);
        A[(af4 * 4 + 1) * SST + arow1] = f2tf(ar1.y);
        A[(af4 * 4 + 2) * SST + arow1] = f2tf(ar1.z);
        A[(af4 * 4 + 3) * SST + arow1] = f2tf(ar1.w);
        uint4 p0 = make_uint4(f2tf(br0.x), f2tf(br0.y), f2tf(br0.z), f2tf(br0.w));
        uint4 p1 = make_uint4(f2tf(br1.x), f2tf(br1.y), f2tf(br1.z), f2tf(br1.w));
        *reinterpret_cast<uint4*>(&Bs[buf][(size_t)brow0 * SST + bf4 * 4]) = p0;
        *reinterpret_cast<uint4*>(&Bs[buf][(size_t)(brow0 + 8) * SST + bf4 * 4]) = p1;
    };

    // ---------- warp/fragment mapping ----------
    const int warp = tid >> 5;
    const int lane = tid & 31;
    const int lg = lane >> 2;          // groupID
    const int lt = lane & 3;           // thread in group
    const int mW = (warp & 1) * 64;    // 2 warps along M
    const int nW = (warp >> 1) * 32;   // 4 warps along N

    float acc[4][4][4];
#pragma unroll
    for (int i = 0; i < 4; ++i)
#pragma unroll
        for (int j = 0; j < 4; ++j)
#pragma unroll
            for (int r = 0; r < 4; ++r) acc[i][j][r] = 0.f;

    auto compute = [&](int buf) {
        const uint32_t* A  = As[buf];
        const uint32_t* Bt = Bs[buf];
#pragma unroll
        for (int ks = 0; ks < 2; ++ks) {
            const int kb = ks * 8;
            uint32_t af[4][4];
#pragma unroll
            for (int i = 0; i < 4; ++i) {
                int col = mW + 16 * i + lg;
                af[i][0] = A[(kb + lt) * SST + col];
                af[i][1] = A[(kb + lt) * SST + col + 8];
                af[i][2] = A[(kb + lt + 4) * SST + col];
                af[i][3] = A[(kb + lt + 4) * SST + col + 8];
            }
            uint32_t bf[4][2];
#pragma unroll
            for (int j = 0; j < 4; ++j) {
                int col = nW + 8 * j + lg;
                bf[j][0] = Bt[(kb + lt) * SST + col];
                bf[j][1] = Bt[(kb + lt + 4) * SST + col];
            }
#pragma unroll
            for (int i = 0; i < 4; ++i)
#pragma unroll
                for (int j = 0; j < 4; ++j)
                    mma_tf32(acc[i][j], af[i], bf[j]);
        }
    };

    // ---------- pipelined mainloop: K = 48 tiles of 16 ----------
    ldg(0);
    sts(0);
    __syncthreads();
    ldg(BK);

#pragma unroll 2
    for (int kt = 0; kt < 46; ++kt) {
        compute(kt & 1);
        sts((kt + 1) & 1);
        __syncthreads();
        ldg((kt + 2) * BK);
    }
    compute(0);   // kt = 46
    sts(1);
    __syncthreads();
    compute(1);   // kt = 47

    // ---------- epilogue: bias gather + average + LeakyReLU ----------
#pragma unroll
    for (int i = 0; i < 4; ++i) {
        const int rbase = m0 + mW + 16 * i + lg;
#pragma unroll
        for (int j = 0; j < 4; ++j) {
            const int c = n0 + nW + 8 * j + lt * 2;
#pragma unroll
            for (int h = 0; h < 2; ++h) {
                const int r = rbase + h * 8;
                if (r < Gd) {
                    size_t biw = ((size_t)ws * Gd + r) * Nd + c;
                    size_t bid = ((size_t)ds * Gd + r) * Nd + c;
                    float2 w2 = *reinterpret_cast<const float2*>(wbsp + biw);
                    float2 d2 = *reinterpret_cast<const float2*>(dbsp + bid);
                    float x0 = acc[i][j][2 * h + 0] + 0.5f * (w2.x + d2.x);
                    float x1 = acc[i][j][2 * h + 1] + 0.5f * (w2.y + d2.y);
                    x0 = x0 > 0.f ? x0 : 0.3f * x0;
                    x1 = x1 > 0.f ? x1 : 0.3f * x1;
                    *reinterpret_cast<float2*>(out + ((size_t)b * Gd + r) * Nd + c) =
                        make_float2(x0, x1);
                }
            }
        }
    }
}

extern "C" void kernel_launch(void* const* d_in, const int* in_sizes, int n_in,
                              void* d_out, int out_size) {
    (void)in_sizes; (void)n_in; (void)out_size;
    const float* inp  = (const float*)d_in[0];
    const int*   week = (const int*)d_in[1];
    const int*   date = (const int*)d_in[2];
    const float* wwsp = (const float*)d_in[3];
    const float* wbsp = (const float*)d_in[4];
    const float* dwsp = (const float*)d_in[5];
    const float* dbsp = (const float*)d_in[6];
    float* out = (float*)d_out;

    dim3 grid(Nd / BN, (Gd + BM - 1) / BM, Bn);  // (6, 3, 64)
    talinear_kernel<<<grid, NTHREADS>>>(inp, week, date, wwsp, wbsp, dwsp, dbsp, out);
}

// round 10
// speedup vs baseline: 1.0022x; 1.0001x over previous
#include <cuda_runtime.h>
#include <cstdint>
#include <cstddef>

// Problem constants
namespace {
constexpr int Bn = 64;      // batch
constexpr int Gd = 307;     // graph dim (M)
constexpr int Ed = 64;
constexpr int Td = 12;
constexpr int Kd = Ed * Td; // 768 contraction
constexpr int Nd = Ed * Td; // 768 output feature
constexpr int BM = 128, BN = 128, BK = 16;
constexpr int SST = 136;    // padded smem row stride (floats): +8 kills frag-LDS bank conflicts
constexpr int NTHREADS = 256;
}

__device__ __forceinline__ uint32_t f2tf(float f) {
    uint32_t u;
    asm("cvt.rna.tf32.f32 %0, %1;" : "=r"(u) : "f"(f));
    return u;
}

__device__ __forceinline__ void mma_tf32(float c[4], const uint32_t a[4], const uint32_t b[2]) {
    asm volatile(
        "mma.sync.aligned.m16n8k8.row.col.f32.tf32.tf32.f32 "
        "{%0,%1,%2,%3}, {%4,%5,%6,%7}, {%8,%9}, {%0,%1,%2,%3};\n"
        : "+f"(c[0]), "+f"(c[1]), "+f"(c[2]), "+f"(c[3])
        : "r"(a[0]), "r"(a[1]), "r"(a[2]), "r"(a[3]), "r"(b[0]), "r"(b[1]));
}

__global__ __launch_bounds__(NTHREADS, 2)
void talinear_kernel(const float* __restrict__ inp,    // [B, G, E, T]
                     const int*   __restrict__ week,   // [B]
                     const int*   __restrict__ date,   // [B]
                     const float* __restrict__ wwsp,   // [7,  T, E, E, T]
                     const float* __restrict__ wbsp,   // [7,  G, E, T]
                     const float* __restrict__ dwsp,   // [288,T, E, E, T]
                     const float* __restrict__ dbsp,   // [288,G, E, T]
                     float*       __restrict__ out)    // [B, G, E, T]
{
    __shared__ __align__(16) uint32_t As[2][BK * SST];  // k-major: [k][m]
    __shared__ __align__(16) uint32_t Bs[2][BK * SST];  // [k][n]

    const int b   = blockIdx.z;
    const int m0  = blockIdx.y * BM;
    const int n0  = blockIdx.x * BN;
    const int tid = threadIdx.x;
    const int ws  = week[b];
    const int ds  = date[b];

    // ---------- global->reg staging mapping ----------
    // A tile: 128 rows x 16 floats = 512 float4, 2 per thread
    const int arow0 = tid >> 2;        // 0..63
    const int arow1 = arow0 + 64;      // 64..127
    const int af4   = tid & 3;         // which float4 within row chunk
    const bool av0  = (m0 + arow0) < Gd;
    const bool av1  = (m0 + arow1) < Gd;
    const float* pa0 = inp + ((size_t)b * Gd + (av0 ? (m0 + arow0) : 0)) * Kd + af4 * 4;
    const float* pa1 = inp + ((size_t)b * Gd + (av1 ? (m0 + arow1) : 0)) * Kd + af4 * 4;

    // B tile: 16 rows x 32 float4 = 512 float4, 2 per thread (rows brow0, brow0+8)
    const int brow0 = tid >> 5;        // 0..7
    const int bf4   = tid & 31;        // 0..31

    float4 ar0, ar1, br0, br1;

    auto ldg = [&](int k0) {
        ar0 = make_float4(0.f, 0.f, 0.f, 0.f);
        ar1 = ar0;
        if (av0) ar0 = *reinterpret_cast<const float4*>(pa0 + k0);
        if (av1) ar1 = *reinterpret_cast<const float4*>(pa1 + k0);
        {
            int k = k0 + brow0;
            int t = k % Td, e = k / Td;
            size_t wo = ((size_t)(ws * Td + t) * Ed + e) * (size_t)Nd + n0 + bf4 * 4;
            size_t dofs = ((size_t)(ds * Td + t) * Ed + e) * (size_t)Nd + n0 + bf4 * 4;
            float4 w = *reinterpret_cast<const float4*>(wwsp + wo);
            float4 d = *reinterpret_cast<const float4*>(dwsp + dofs);
            br0 = make_float4(0.5f * (w.x + d.x), 0.5f * (w.y + d.y),
                              0.5f * (w.z + d.z), 0.5f * (w.w + d.w));
        }
        {
            int k = k0 + brow0 + 8;
            int t = k % Td, e = k / Td;
            size_t wo = ((size_t)(ws * Td + t) * Ed + e) * (size_t)Nd + n0 + bf4 * 4;
            size_t dofs = ((size_t)(ds * Td + t) * Ed + e) * (size_t)Nd + n0 + bf4 * 4;
            float4 w = *reinterpret_cast<const float4*>(wwsp + wo);
            float4 d = *reinterpret_cast<const float4*>(dwsp + dofs);
            br1 = make_float4(0.5f * (w.x + d.x), 0.5f * (w.y + d.y),
                              0.5f * (w.z + d.z), 0.5f * (w.w + d.w));
        }
    };

    auto sts = [&](int buf) {
        uint32_t* A = As[buf];
        // transposed scatter: As[k][m], convert to tf32 once per element
        A[(af4 * 4 + 0) * SST + arow0] = f2tf(ar0.x);
        A[(af4 * 4 + 1) * SST + arow0] = f2tf(ar0.y);
        A[(af4 * 4 + 2) * SST + arow0] = f2tf(ar0.z);
        A[(af4 * 4 + 3) * SST + arow0] = f2tf(ar0.w);
        A[(af4 * 4 + 0) * SST + arow1] = f2tf(ar1.x);
        A[(af4 * 4 + 1) * SST + arow1] = f2tf(ar1.y);
        A[(af4 * 4 + 2) * SST + arow1] = f2tf(ar1.z);
        A[(af4 * 4 + 3) * SST + arow1] = f2tf(ar1.w);
        uint4 p0 = make_uint4(f2tf(br0.x), f2tf(br0.y), f2tf(br0.z), f2tf(br0.w));
        uint4 p1 = make_uint4(f2tf(br1.x), f2tf(br1.y), f2tf(br1.z), f2tf(br1.w));
        *reinterpret_cast<uint4*>(&Bs[buf][(size_t)brow0 * SST + bf4 * 4]) = p0;
        *reinterpret_cast<uint4*>(&Bs[buf][(size_t)(brow0 + 8) * SST + bf4 * 4]) = p1;
    };

    // ---------- warp/fragment mapping ----------
    const int warp = tid >> 5;
    const int lane = tid & 31;
    const int lg = lane >> 2;          // groupID
    const int lt = lane & 3;           // thread in group
    const int mW = (warp & 1) * 64;    // 2 warps along M
    const int nW = (warp >> 1) * 32;   // 4 warps along N

    float acc[4][4][4];
#pragma unroll
    for (int i = 0; i < 4; ++i)
#pragma unroll
        for (int j = 0; j < 4; ++j)
#pragma unroll
            for (int r = 0; r < 4; ++r) acc[i][j][r] = 0.f;

    auto compute = [&](int buf) {
        const uint32_t* A  = As[buf];
        const uint32_t* Bt = Bs[buf];
#pragma unroll
        for (int ks = 0; ks < 2; ++ks) {
            const int kb = ks * 8;
            uint32_t af[4][4];
#pragma unroll
            for (int i = 0; i < 4; ++i) {
                int col = mW + 16 * i + lg;
                af[i][0] = A[(kb + lt) * SST + col];
                af[i][1] = A[(kb + lt) * SST + col + 8];
                af[i][2] = A[(kb + lt + 4) * SST + col];
                af[i][3] = A[(kb + lt + 4) * SST + col + 8];
            }
            uint32_t bf[4][2];
#pragma unroll
            for (int j = 0; j < 4; ++j) {
                int col = nW + 8 * j + lg;
                bf[j][0] = Bt[(kb + lt) * SST + col];
                bf[j][1] = Bt[(kb + lt + 4) * SST + col];
            }
#pragma unroll
            for (int i = 0; i < 4; ++i)
#pragma unroll
                for (int j = 0; j < 4; ++j)
                    mma_tf32(acc[i][j], af[i], bf[j]);
        }
    };

    // ---------- pipelined mainloop: K = 48 tiles of 16 ----------
    ldg(0);
    sts(0);
    __syncthreads();
    ldg(BK);

#pragma unroll 2
    for (int kt = 0; kt < 46; ++kt) {
        compute(kt & 1);
        sts((kt + 1) & 1);
        __syncthreads();
        ldg((kt + 2) * BK);
    }
    compute(0);   // kt = 46
    sts(1);
    __syncthreads();
    compute(1);   // kt = 47

    // ---------- epilogue: bias gather + average + LeakyReLU ----------
#pragma unroll
    for (int i = 0; i < 4; ++i) {
        const int rbase = m0 + mW + 16 * i + lg;
#pragma unroll
        for (int j = 0; j < 4; ++j) {
            const int c = n0 + nW + 8 * j + lt * 2;
#pragma unroll
            for (int h = 0; h < 2; ++h) {
                const int r = rbase + h * 8;
                if (r < Gd) {
                    size_t biw = ((size_t)ws * Gd + r) * Nd + c;
                    size_t bid = ((size_t)ds * Gd + r) * Nd + c;
                    float2 w2 = *reinterpret_cast<const float2*>(wbsp + biw);
                    float2 d2 = *reinterpret_cast<const float2*>(dbsp + bid);
                    float x0 = acc[i][j][2 * h + 0] + 0.5f * (w2.x + d2.x);
                    float x1 = acc[i][j][2 * h + 1] + 0.5f * (w2.y + d2.y);
                    x0 = x0 > 0.f ? x0 : 0.3f * x0;
                    x1 = x1 > 0.f ? x1 : 0.3f * x1;
                    *reinterpret_cast<float2*>(out + ((size_t)b * Gd + r) * Nd + c) =
                        make_float2(x0, x1);
                }
            }
        }
    }
}

extern "C" void kernel_launch(void* const* d_in, const int* in_sizes, int n_in,
                              void* d_out, int out_size) {
    (void)in_sizes; (void)n_in; (void)out_size;
    const float* inp  = (const float*)d_in[0];
    const int*   week = (const int*)d_in[1];
    const int*   date = (const int*)d_in[2];
    const float* wwsp = (const float*)d_in[3];
    const float* wbsp = (const float*)d_in[4];
    const float* dwsp = (const float*)d_in[5];
    const float* dbsp = (const float*)d_in[6];
    float* out = (float*)d_out;

    dim3 grid(Nd / BN, (Gd + BM - 1) / BM, Bn);  // (6, 3, 64)
    talinear_kernel<<<grid, NTHREADS>>>(inp, week, date, wwsp, wbsp, dwsp, dbsp, out);
}